// round 14
// baseline (speedup 1.0000x reference)
#include <cuda_runtime.h>
#include <cuda_bf16.h>
#include <cstdint>

#define N 8192
#define NIN 64
#define NH 128
#define CAP 128   // max degree capacity; deg ~ Poisson(16), P(>100) ~ 0

// ---------------- device scratch (no allocations allowed) ----------------
// NOTE: d_col_cnt / d_t1 are zero at module load and re-zeroed by k7_reset at
// the END of every kernel_launch invocation (after their last readers), so the
// "counters are zero" precondition holds for every call. Deterministic.
__device__ float d_hp[N * NIN];      // transformed features
__device__ float d_as[N];            // source attention terms
__device__ float d_ad[N];            // dst attention terms
__device__ float d_attr[N];          // attribute recon error per row
__device__ float d_emb[N * NIN];     // GAT output embeddings (fp32, for sparse path)
__device__ __nv_bfloat16 d_embh[N * NIN];  // bf16 copy for tensor-core GEMM
__device__ float d_t1[N];            // sum_j sigmoid(z)^2 per row
__device__ float d_t2[N];            // sum_{j in nbr} sigmoid(z) per row
__device__ int   d_col_cnt[N];
__device__ int   d_col_list[N * CAP];  // sources i per column j
__device__ int   d_row_cnt[N];
__device__ int   d_row_list[N * CAP];  // dsts j per row r

// ---- host-side stream/event resources (created once; no device memory) ----
struct GraphRes {
    cudaStream_t s1;
    cudaEvent_t e_fork, e_join, e_k3, e_t2;
    GraphRes() {
        cudaStreamCreateWithFlags(&s1, cudaStreamNonBlocking);
        cudaEventCreateWithFlags(&e_fork, cudaEventDisableTiming);
        cudaEventCreateWithFlags(&e_join, cudaEventDisableTiming);
        cudaEventCreateWithFlags(&e_k3, cudaEventDisableTiming);
        cudaEventCreateWithFlags(&e_t2, cudaEventDisableTiming);
    }
};
static GraphRes g_res;

// ---------------- K1: fused MLP branches, weights staged in smem ----------------
#define K1_SSEQ 0
#define K1_ACT1 (32 * 68)
#define K1_ACT2 (K1_ACT1 + 32 * 132)
#define K1_W    (K1_ACT2 + 32 * 132)
#define K1_FLOATS (K1_W + 128 * 68)

__global__ __launch_bounds__(256) void k1_mlp(
    const float* __restrict__ seq1,
    const float* __restrict__ Wst, const float* __restrict__ bst,
    const float* __restrict__ Wg,
    const float* __restrict__ asrc, const float* __restrict__ adst,
    const float* __restrict__ Wa1, const float* __restrict__ ba1,
    const float* __restrict__ Wa2, const float* __restrict__ ba2)
{
    extern __shared__ __align__(16) float sm[];
    float* sseq = sm + K1_SSEQ;
    float* sW   = sm + K1_W;
    const int tid = threadIdx.x;
    const int r0 = blockIdx.x * 32;

    for (int idx = tid; idx < 32 * 16; idx += 256) {
        int row = idx >> 4, k4 = (idx & 15) << 2;
        float4 v = *(const float4*)&seq1[(r0 + row) * 64 + k4];
        float* p = &sseq[row * 68 + k4];
        p[0] = v.x; p[1] = v.y; p[2] = v.z; p[3] = v.w;
    }

    // ---- phase 1 (x2 branches): 64 -> 128 ----
    #pragma unroll
    for (int br = 0; br < 2; br++) {
        const float* W = br ? Wa1 : Wst;
        const float* bb = br ? ba1 : bst;
        float* sAct = sm + (br ? K1_ACT2 : K1_ACT1);
        __syncthreads();
        for (int idx = tid; idx < 128 * 16; idx += 256) {
            int row = idx >> 4, k4 = (idx & 15) << 2;
            float4 v = *(const float4*)&W[row * 64 + k4];
            float* p = &sW[row * 68 + k4];
            p[0] = v.x; p[1] = v.y; p[2] = v.z; p[3] = v.w;
        }
        __syncthreads();

        int tx = tid & 31, ty = tid >> 5;
        float acc[4][4];
        #pragma unroll
        for (int j = 0; j < 4; j++) {
            float b = bb[tx * 4 + j];
            #pragma unroll
            for (int i = 0; i < 4; i++) acc[i][j] = b;
        }
        for (int k4 = 0; k4 < 64; k4 += 4) {
            float4 a[4];
            #pragma unroll
            for (int i = 0; i < 4; i++)
                a[i] = *(const float4*)&sseq[(ty * 4 + i) * 68 + k4];
            #pragma unroll
            for (int j = 0; j < 4; j++) {
                float4 w = *(const float4*)&sW[(tx * 4 + j) * 68 + k4];
                #pragma unroll
                for (int i = 0; i < 4; i++)
                    acc[i][j] += a[i].x * w.x + a[i].y * w.y + a[i].z * w.z + a[i].w * w.w;
            }
        }
        #pragma unroll
        for (int i = 0; i < 4; i++)
            #pragma unroll
            for (int j = 0; j < 4; j++)
                sAct[(ty * 4 + i) * 132 + tx * 4 + j] = fmaxf(acc[i][j], 0.f);
    }

    // ---- phase 2 (x2 branches): 128 -> 64 ----
    #pragma unroll
    for (int br = 0; br < 2; br++) {
        const float* W = br ? Wa2 : Wg;
        float* sAct = sm + (br ? K1_ACT2 : K1_ACT1);
        __syncthreads();
        for (int idx = tid; idx < 64 * 32; idx += 256) {
            int row = idx >> 5, k4 = (idx & 31) << 2;
            float4 v = *(const float4*)&W[row * 128 + k4];
            float* p = &sW[row * 132 + k4];
            p[0] = v.x; p[1] = v.y; p[2] = v.z; p[3] = v.w;
        }
        __syncthreads();

        int tx = tid & 15, ty = tid >> 4;
        float acc[2][4];
        #pragma unroll
        for (int j = 0; j < 4; j++) {
            float b = br ? ba2[tx * 4 + j] : 0.f;
            acc[0][j] = b; acc[1][j] = b;
        }
        for (int k4 = 0; k4 < 128; k4 += 4) {
            float4 a0 = *(const float4*)&sAct[(ty * 2 + 0) * 132 + k4];
            float4 a1 = *(const float4*)&sAct[(ty * 2 + 1) * 132 + k4];
            #pragma unroll
            for (int j = 0; j < 4; j++) {
                float4 w = *(const float4*)&sW[(tx * 4 + j) * 132 + k4];
                acc[0][j] += a0.x * w.x + a0.y * w.y + a0.z * w.z + a0.w * w.w;
                acc[1][j] += a1.x * w.x + a1.y * w.y + a1.z * w.z + a1.w * w.w;
            }
        }
        __syncthreads();
        #pragma unroll
        for (int i = 0; i < 2; i++)
            #pragma unroll
            for (int j = 0; j < 4; j++)
                sAct[(ty * 2 + i) * 132 + tx * 4 + j] = acc[i][j];
    }
    __syncthreads();

    // ---- per-row reductions ----
    {
        float* sh  = sm + K1_ACT1;
        float* sxa = sm + K1_ACT2;
        int warp = tid >> 5, lane = tid & 31;
        float as0 = asrc[lane], as1 = asrc[lane + 32];
        float ad0 = adst[lane], ad1 = adst[lane + 32];
        for (int rr = 0; rr < 4; rr++) {
            int row = warp * 4 + rr;
            float hp0 = sh[row * 132 + lane], hp1 = sh[row * 132 + lane + 32];
            float x0 = sxa[row * 132 + lane], x1 = sxa[row * 132 + lane + 32];
            float df0 = sseq[row * 68 + lane] - x0;
            float df1 = sseq[row * 68 + lane + 32] - x1;
            float sA = hp0 * as0 + hp1 * as1;
            float sD = hp0 * ad0 + hp1 * ad1;
            float sE = df0 * df0 + df1 * df1;
            #pragma unroll
            for (int o = 16; o; o >>= 1) {
                sA += __shfl_xor_sync(0xffffffffu, sA, o);
                sD += __shfl_xor_sync(0xffffffffu, sD, o);
                sE += __shfl_xor_sync(0xffffffffu, sE, o);
            }
            if (lane == 0) {
                d_as[r0 + row] = sA;
                d_ad[r0 + row] = sD;
                d_attr[r0 + row] = sqrtf(sE);
            }
            d_hp[(r0 + row) * 64 + lane]      = hp0;
            d_hp[(r0 + row) * 64 + lane + 32] = hp1;
        }
    }
}

// ---------------- K2: streaming adj scan (best measured) ----------
__global__ __launch_bounds__(256) void k2_adj(const float* __restrict__ adj)
{
    const int r = blockIdx.x;
    const int tid = threadIdx.x;
    __shared__ int s_cnt;
    __shared__ int s_list[CAP];
    if (tid == 0) s_cnt = 0;
    __syncthreads();
    const float4* row = (const float4*)(adj + (size_t)r * N);

    float4 v[8];
    #pragma unroll
    for (int it = 0; it < 8; it++)
        v[it] = __ldcs(&row[tid + it * 256]);

    #pragma unroll
    for (int it = 0; it < 8; it++) {
        int jb = (tid + it * 256) << 2;
        if (v[it].x > 0.f) { int p = atomicAdd(&s_cnt, 1); if (p < CAP) s_list[p] = jb; }
        if (v[it].y > 0.f) { int p = atomicAdd(&s_cnt, 1); if (p < CAP) s_list[p] = jb + 1; }
        if (v[it].z > 0.f) { int p = atomicAdd(&s_cnt, 1); if (p < CAP) s_list[p] = jb + 2; }
        if (v[it].w > 0.f) { int p = atomicAdd(&s_cnt, 1); if (p < CAP) s_list[p] = jb + 3; }
    }
    __syncthreads();
    int cnt = min(s_cnt, CAP);
    if (tid == 0) d_row_cnt[r] = cnt;
    for (int t = tid; t < cnt; t += 256) {
        int j = s_list[t];
        d_row_list[r * CAP + t] = j;
        int slot = atomicAdd(&d_col_cnt[j], 1);
        if (slot < CAP) d_col_list[j * CAP + slot] = r;
    }
}

// ---------------- K3: sparse masked softmax over sources + emb ----------------
__global__ __launch_bounds__(256) void k3_attn(const float* __restrict__ bgat)
{
    __shared__ float sh_e[8][CAP];
    __shared__ int   sh_i[8][CAP];
    const int lane = threadIdx.x & 31;
    const int wl = threadIdx.x >> 5;
    const int j = blockIdx.x * 8 + wl;
    int cnt = min(d_col_cnt[j], CAP);
    float adv = d_ad[j];
    float m = -1e30f;
    for (int t = lane; t < cnt; t += 32) {
        int i = d_col_list[j * CAP + t];
        float e = d_as[i] + adv;
        e = e > 0.f ? e : 0.2f * e;     // leaky_relu(0.2)
        sh_e[wl][t] = e; sh_i[wl][t] = i;
        m = fmaxf(m, e);
    }
    float eself = d_as[j] + adv; eself = eself > 0.f ? eself : 0.2f * eself;
    m = fmaxf(m, eself);
    #pragma unroll
    for (int o = 16; o; o >>= 1) m = fmaxf(m, __shfl_xor_sync(0xffffffffu, m, o));
    float wsum = (lane == 0) ? __expf(eself - m) : 0.f;
    for (int t = lane; t < cnt; t += 32) {
        float ex = __expf(sh_e[wl][t] - m);
        sh_e[wl][t] = ex;
        wsum += ex;
    }
    #pragma unroll
    for (int o = 16; o; o >>= 1) wsum += __shfl_xor_sync(0xffffffffu, wsum, o);
    __syncwarp();
    float inv = __fdividef(1.f, wsum);
    float exself = __expf(eself - m);
    float acc0 = exself * d_hp[j * 64 + lane];
    float acc1 = exself * d_hp[j * 64 + lane + 32];
    for (int t = 0; t < cnt; t++) {
        int i = sh_i[wl][t];
        float ex = sh_e[wl][t];
        acc0 += ex * d_hp[i * 64 + lane];
        acc1 += ex * d_hp[i * 64 + lane + 32];
    }
    float e0 = acc0 * inv + bgat[lane];
    float e1 = acc1 * inv + bgat[lane + 32];
    d_emb[j * 64 + lane]      = e0;
    d_emb[j * 64 + lane + 32] = e1;
    d_embh[j * 64 + lane]      = __float2bfloat16(e0);
    d_embh[j * 64 + lane + 32] = __float2bfloat16(e1);
}

// ---------------- K4: symmetric emb@emb^T, low-register variant --------------
#define TPAD 72

__device__ __forceinline__ void ldsm4(uint32_t& r0, uint32_t& r1, uint32_t& r2,
                                      uint32_t& r3, const void* p)
{
    uint32_t addr = (uint32_t)__cvta_generic_to_shared(p);
    asm volatile("ldmatrix.sync.aligned.m8n8.x4.shared.b16 {%0,%1,%2,%3}, [%4];"
                 : "=r"(r0), "=r"(r1), "=r"(r2), "=r"(r3) : "r"(addr));
}

__device__ __forceinline__ void mma16816(float* c, const uint32_t* a,
                                         uint32_t b0, uint32_t b1)
{
    asm volatile(
        "mma.sync.aligned.m16n8k16.row.col.f32.bf16.bf16.f32 "
        "{%0,%1,%2,%3}, {%4,%5,%6,%7}, {%8,%9}, {%0,%1,%2,%3};"
        : "+f"(c[0]), "+f"(c[1]), "+f"(c[2]), "+f"(c[3])
        : "r"(a[0]), "r"(a[1]), "r"(a[2]), "r"(a[3]), "r"(b0), "r"(b1));
}

// sigmoid(z)^2 via single-MUFU tanh.approx: sig = 0.5 + 0.5*tanh(z/2)
__device__ __forceinline__ float sig2_fast(float z) {
    float t;
    asm("tanh.approx.f32 %0, %1;" : "=f"(t) : "f"(0.5f * z));
    float s = fmaf(0.5f, t, 0.5f);
    return s * s;
}

__global__ __launch_bounds__(256) void k4_tri()
{
    const int bi = blockIdx.x, bj = blockIdx.y;
    if (bj < bi) return;                    // upper triangle only
    const bool diag = (bi == bj);

    __shared__ __align__(16) __nv_bfloat16 sA[128 * TPAD];
    __shared__ __align__(16) __nv_bfloat16 sB[128 * TPAD];
    __shared__ float scol[8][128];          // per-warp column sums (no atomics)
    const int tid = threadIdx.x;
    const int lane = tid & 31, w = tid >> 5;
    const int r0 = bi * 128, c0 = bj * 128;

    #pragma unroll
    for (int it = 0; it < 4; it++) {
        int idx = tid + it * 256;
        int row = idx >> 3, kc = (idx & 7) * 8;
        *(uint4*)&sA[row * TPAD + kc] = *(const uint4*)&d_embh[(r0 + row) * 64 + kc];
    }
    if (!diag) {
        #pragma unroll
        for (int it = 0; it < 4; it++) {
            int idx = tid + it * 256;
            int row = idx >> 3, kc = (idx & 7) * 8;
            *(uint4*)&sB[row * TPAD + kc] = *(const uint4*)&d_embh[(c0 + row) * 64 + kc];
        }
    }
    __syncthreads();

    const __nv_bfloat16* Bp = diag ? sA : sB;

    uint32_t aF[4][4];
    {
        int m = lane >> 3, rr = lane & 7;
        int arow = 16 * w + rr + (m & 1) * 8;
        int koff = (m >> 1) * 8;
        #pragma unroll
        for (int s = 0; s < 4; s++)
            ldsm4(aF[s][0], aF[s][1], aF[s][2], aF[s][3],
                  &sA[arow * TPAD + s * 16 + koff]);
    }

    const int m = lane >> 3, rr = lane & 7;
    const int brow = rr + ((m >> 1) & 1) * 8;
    const int bkoff = (m & 1) * 8;

    float racc0 = 0.f, racc1 = 0.f;

    #pragma unroll
    for (int fp = 0; fp < 8; fp++) {
        float acc2[2][4];
        #pragma unroll
        for (int i = 0; i < 2; i++)
            #pragma unroll
            for (int q = 0; q < 4; q++) acc2[i][q] = 0.f;

        #pragma unroll
        for (int s = 0; s < 4; s++) {
            uint32_t b0, b1, b2, b3;
            ldsm4(b0, b1, b2, b3,
                  &Bp[(fp * 16 + brow) * TPAD + s * 16 + bkoff]);
            mma16816(acc2[0], aF[s], b0, b1);
            mma16816(acc2[1], aF[s], b2, b3);
        }

        #pragma unroll
        for (int i = 0; i < 2; i++) {
            float v0 = sig2_fast(acc2[i][0]), v1 = sig2_fast(acc2[i][1]);
            float v2 = sig2_fast(acc2[i][2]), v3 = sig2_fast(acc2[i][3]);
            racc0 += v0 + v1;
            racc1 += v2 + v3;
            if (!diag) {
                float cs0 = v0 + v2, cs1 = v1 + v3;
                cs0 += __shfl_xor_sync(0xffffffffu, cs0, 4);
                cs0 += __shfl_xor_sync(0xffffffffu, cs0, 8);
                cs0 += __shfl_xor_sync(0xffffffffu, cs0, 16);
                cs1 += __shfl_xor_sync(0xffffffffu, cs1, 4);
                cs1 += __shfl_xor_sync(0xffffffffu, cs1, 8);
                cs1 += __shfl_xor_sync(0xffffffffu, cs1, 16);
                if (lane < 4) {
                    int colb = fp * 16 + i * 8 + lane * 2;
                    scol[w][colb]     = cs0;
                    scol[w][colb + 1] = cs1;
                }
            }
        }
    }

    racc0 += __shfl_xor_sync(0xffffffffu, racc0, 1);
    racc0 += __shfl_xor_sync(0xffffffffu, racc0, 2);
    racc1 += __shfl_xor_sync(0xffffffffu, racc1, 1);
    racc1 += __shfl_xor_sync(0xffffffffu, racc1, 2);
    if ((lane & 3) == 0) {
        int row = r0 + 16 * w + (lane >> 2);
        atomicAdd(&d_t1[row], racc0);
        atomicAdd(&d_t1[row + 8], racc1);
    }

    if (!diag) {
        __syncthreads();
        if (tid < 128) {
            float s = scol[0][tid] + scol[1][tid] + scol[2][tid] + scol[3][tid]
                    + scol[4][tid] + scol[5][tid] + scol[6][tid] + scol[7][tid];
            atomicAdd(&d_t1[c0 + tid], s);
        }
    }
}

// ---------------- K5: sparse t2 correction (overlapped with K4 on s1) ---------
__global__ __launch_bounds__(256) void k5_t2()
{
    const int lane = threadIdx.x & 31;
    const int r = blockIdx.x * 8 + (threadIdx.x >> 5);
    float e0 = d_emb[r * 64 + lane], e1 = d_emb[r * 64 + lane + 32];
    int cnt = d_row_cnt[r];
    float t2 = 0.f;
    for (int t = 0; t < cnt; t++) {
        int j = d_row_list[r * CAP + t];
        float p = e0 * d_emb[j * 64 + lane] + e1 * d_emb[j * 64 + lane + 32];
        #pragma unroll
        for (int o = 16; o; o >>= 1) p += __shfl_xor_sync(0xffffffffu, p, o);
        float u = __expf(-p);
        t2 += __fdividef(1.f, 1.f + u);
    }
    if (lane == 0) d_t2[r] = t2;
}

// ---------------- K6: fused score + loss + gather ----------------
__device__ __forceinline__ float node_score(int r) {
    float v = d_t1[r] - 2.f * d_t2[r] + (float)d_row_cnt[r];
    return 0.5f * d_attr[r] + 0.5f * sqrtf(fmaxf(v, 0.f));
}

__global__ void k6_out(const int* __restrict__ idxt, const int* __restrict__ idxs,
                       float* __restrict__ out)
{
    int tid = threadIdx.x;
    if (blockIdx.x == 0) {
        __shared__ float red[256];
        float s = 0.f;
        for (int i = tid; i < 4096; i += 256) s += node_score(idxt[i]);
        red[tid] = s; __syncthreads();
        for (int o = 128; o; o >>= 1) { if (tid < o) red[tid] += red[tid + o]; __syncthreads(); }
        if (tid == 0) out[0] = red[0] * (1.f / 4096.f);
    } else {
        int i = (blockIdx.x - 1) * 256 + tid;
        out[1 + i] = node_score(idxs[i]);
    }
}

// ---------------- K7: trailing reset — restores zero-state for next call -----
__global__ void k7_reset() {
    int i = blockIdx.x * blockDim.x + threadIdx.x;
    if (i < N) { d_col_cnt[i] = 0; d_t1[i] = 0.f; }
}

// ---------------- launch ----------------
extern "C" void kernel_launch(void* const* d_in, const int* in_sizes, int n_in,
                              void* d_out, int out_size)
{
    const float* seq1    = (const float*)d_in[0];
    const float* adj     = (const float*)d_in[1];
    const int* idx_train = (const int*)d_in[2];
    const int* idx_test  = (const int*)d_in[3];
    const float* W_stru  = (const float*)d_in[4];
    const float* b_stru  = (const float*)d_in[5];
    const float* W_gat   = (const float*)d_in[6];
    const float* att_src = (const float*)d_in[7];
    const float* att_dst = (const float*)d_in[8];
    const float* b_gat   = (const float*)d_in[9];
    const float* W_a1    = (const float*)d_in[10];
    const float* b_a1    = (const float*)d_in[11];
    const float* W_a2    = (const float*)d_in[12];
    const float* b_a2    = (const float*)d_in[13];
    float* out = (float*)d_out;

    const int k1_smem = K1_FLOATS * (int)sizeof(float);   // ~77.3 KB
    cudaFuncSetAttribute(k1_mlp, cudaFuncAttributeMaxDynamicSharedMemorySize, k1_smem);

    // fork 1: k1 (compute-bound, s1) concurrent with k2 (HBM-bound, stream 0).
    // col_cnt/t1 are pre-zeroed (module init / previous call's k7_reset).
    cudaEventRecord(g_res.e_fork, 0);
    cudaStreamWaitEvent(g_res.s1, g_res.e_fork, 0);
    k1_mlp<<<256, 256, k1_smem, g_res.s1>>>(seq1, W_stru, b_stru, W_gat,    // #1
                                            att_src, att_dst,
                                            W_a1, b_a1, W_a2, b_a2);
    cudaEventRecord(g_res.e_join, g_res.s1);

    k2_adj<<<8192, 256>>>(adj);                                             // #2

    // join 1, then attention
    cudaStreamWaitEvent(0, g_res.e_join, 0);
    k3_attn<<<1024, 256>>>(b_gat);                                          // #3

    // fork 2 around k4: submit k4 FOURTH so ncu's capture window lands on it
    cudaEventRecord(g_res.e_k3, 0);
    k4_tri<<<dim3(64, 64), 256>>>();                                        // #4

    cudaStreamWaitEvent(g_res.s1, g_res.e_k3, 0);
    k5_t2<<<1024, 256, 0, g_res.s1>>>();                                    // #5
    cudaEventRecord(g_res.e_t2, g_res.s1);

    // join 2, then fused score/output, then trailing reset
    cudaStreamWaitEvent(0, g_res.e_t2, 0);
    k6_out<<<17, 256>>>(idx_train, idx_test, out);                          // #6
    k7_reset<<<32, 256>>>();                                                // #7
}

// round 15
// speedup vs baseline: 1.0285x; 1.0285x over previous
#include <cuda_runtime.h>
#include <cuda_bf16.h>
#include <cstdint>

#define N 8192
#define NIN 64
#define NH 128
#define CAP 128   // max degree capacity; deg ~ Poisson(16), P(>100) ~ 0

// ---------------- device scratch (no allocations allowed) ----------------
// d_col_cnt / d_t1 are zero at module load and re-zeroed by k7_reset at the
// END of every kernel_launch (after their last readers). Deterministic.
__device__ float d_hp[N * NIN];      // transformed features
__device__ float d_as[N];            // source attention terms
__device__ float d_ad[N];            // dst attention terms
__device__ float d_attr[N];          // attribute recon error per row
__device__ float d_emb[N * NIN];     // GAT output embeddings (fp32, for sparse path)
__device__ __nv_bfloat16 d_embh[N * NIN];  // bf16 copy for tensor-core GEMM
__device__ float d_t1[N];            // sum_j sigmoid(z)^2 per row
__device__ float d_t2[N];            // sum_{j in nbr} sigmoid(z) per row
__device__ int   d_col_cnt[N];
__device__ int   d_col_list[N * CAP];  // sources i per column j
__device__ int   d_row_cnt[N];
__device__ int   d_row_list[N * CAP];  // dsts j per row r

// ---- host-side stream/event resources (created once; no device memory) ----
struct GraphRes {
    cudaStream_t s1;
    cudaEvent_t e_fork, e_join, e_k3, e_t2;
    GraphRes() {
        cudaStreamCreateWithFlags(&s1, cudaStreamNonBlocking);
        cudaEventCreateWithFlags(&e_fork, cudaEventDisableTiming);
        cudaEventCreateWithFlags(&e_join, cudaEventDisableTiming);
        cudaEventCreateWithFlags(&e_k3, cudaEventDisableTiming);
        cudaEventCreateWithFlags(&e_t2, cudaEventDisableTiming);
    }
};
static GraphRes g_res;

// ---------------- K1: fused MLP branches, weights staged in smem ----------------
#define K1_SSEQ 0
#define K1_ACT1 (32 * 68)
#define K1_ACT2 (K1_ACT1 + 32 * 132)
#define K1_W    (K1_ACT2 + 32 * 132)
#define K1_FLOATS (K1_W + 128 * 68)

__global__ __launch_bounds__(256) void k1_mlp(
    const float* __restrict__ seq1,
    const float* __restrict__ Wst, const float* __restrict__ bst,
    const float* __restrict__ Wg,
    const float* __restrict__ asrc, const float* __restrict__ adst,
    const float* __restrict__ Wa1, const float* __restrict__ ba1,
    const float* __restrict__ Wa2, const float* __restrict__ ba2)
{
    extern __shared__ __align__(16) float sm[];
    float* sseq = sm + K1_SSEQ;
    float* sW   = sm + K1_W;
    const int tid = threadIdx.x;
    const int r0 = blockIdx.x * 32;

    for (int idx = tid; idx < 32 * 16; idx += 256) {
        int row = idx >> 4, k4 = (idx & 15) << 2;
        float4 v = *(const float4*)&seq1[(r0 + row) * 64 + k4];
        float* p = &sseq[row * 68 + k4];
        p[0] = v.x; p[1] = v.y; p[2] = v.z; p[3] = v.w;
    }

    // ---- phase 1 (x2 branches): 64 -> 128 ----
    #pragma unroll
    for (int br = 0; br < 2; br++) {
        const float* W = br ? Wa1 : Wst;
        const float* bb = br ? ba1 : bst;
        float* sAct = sm + (br ? K1_ACT2 : K1_ACT1);
        __syncthreads();
        for (int idx = tid; idx < 128 * 16; idx += 256) {
            int row = idx >> 4, k4 = (idx & 15) << 2;
            float4 v = *(const float4*)&W[row * 64 + k4];
            float* p = &sW[row * 68 + k4];
            p[0] = v.x; p[1] = v.y; p[2] = v.z; p[3] = v.w;
        }
        __syncthreads();

        int tx = tid & 31, ty = tid >> 5;
        float acc[4][4];
        #pragma unroll
        for (int j = 0; j < 4; j++) {
            float b = bb[tx * 4 + j];
            #pragma unroll
            for (int i = 0; i < 4; i++) acc[i][j] = b;
        }
        for (int k4 = 0; k4 < 64; k4 += 4) {
            float4 a[4];
            #pragma unroll
            for (int i = 0; i < 4; i++)
                a[i] = *(const float4*)&sseq[(ty * 4 + i) * 68 + k4];
            #pragma unroll
            for (int j = 0; j < 4; j++) {
                float4 w = *(const float4*)&sW[(tx * 4 + j) * 68 + k4];
                #pragma unroll
                for (int i = 0; i < 4; i++)
                    acc[i][j] += a[i].x * w.x + a[i].y * w.y + a[i].z * w.z + a[i].w * w.w;
            }
        }
        #pragma unroll
        for (int i = 0; i < 4; i++)
            #pragma unroll
            for (int j = 0; j < 4; j++)
                sAct[(ty * 4 + i) * 132 + tx * 4 + j] = fmaxf(acc[i][j], 0.f);
    }

    // ---- phase 2 (x2 branches): 128 -> 64 ----
    #pragma unroll
    for (int br = 0; br < 2; br++) {
        const float* W = br ? Wa2 : Wg;
        float* sAct = sm + (br ? K1_ACT2 : K1_ACT1);
        __syncthreads();
        for (int idx = tid; idx < 64 * 32; idx += 256) {
            int row = idx >> 5, k4 = (idx & 31) << 2;
            float4 v = *(const float4*)&W[row * 128 + k4];
            float* p = &sW[row * 132 + k4];
            p[0] = v.x; p[1] = v.y; p[2] = v.z; p[3] = v.w;
        }
        __syncthreads();

        int tx = tid & 15, ty = tid >> 4;
        float acc[2][4];
        #pragma unroll
        for (int j = 0; j < 4; j++) {
            float b = br ? ba2[tx * 4 + j] : 0.f;
            acc[0][j] = b; acc[1][j] = b;
        }
        for (int k4 = 0; k4 < 128; k4 += 4) {
            float4 a0 = *(const float4*)&sAct[(ty * 2 + 0) * 132 + k4];
            float4 a1 = *(const float4*)&sAct[(ty * 2 + 1) * 132 + k4];
            #pragma unroll
            for (int j = 0; j < 4; j++) {
                float4 w = *(const float4*)&sW[(tx * 4 + j) * 132 + k4];
                acc[0][j] += a0.x * w.x + a0.y * w.y + a0.z * w.z + a0.w * w.w;
                acc[1][j] += a1.x * w.x + a1.y * w.y + a1.z * w.z + a1.w * w.w;
            }
        }
        __syncthreads();
        #pragma unroll
        for (int i = 0; i < 2; i++)
            #pragma unroll
            for (int j = 0; j < 4; j++)
                sAct[(ty * 2 + i) * 132 + tx * 4 + j] = acc[i][j];
    }
    __syncthreads();

    // ---- per-row reductions ----
    {
        float* sh  = sm + K1_ACT1;
        float* sxa = sm + K1_ACT2;
        int warp = tid >> 5, lane = tid & 31;
        float as0 = asrc[lane], as1 = asrc[lane + 32];
        float ad0 = adst[lane], ad1 = adst[lane + 32];
        for (int rr = 0; rr < 4; rr++) {
            int row = warp * 4 + rr;
            float hp0 = sh[row * 132 + lane], hp1 = sh[row * 132 + lane + 32];
            float x0 = sxa[row * 132 + lane], x1 = sxa[row * 132 + lane + 32];
            float df0 = sseq[row * 68 + lane] - x0;
            float df1 = sseq[row * 68 + lane + 32] - x1;
            float sA = hp0 * as0 + hp1 * as1;
            float sD = hp0 * ad0 + hp1 * ad1;
            float sE = df0 * df0 + df1 * df1;
            #pragma unroll
            for (int o = 16; o; o >>= 1) {
                sA += __shfl_xor_sync(0xffffffffu, sA, o);
                sD += __shfl_xor_sync(0xffffffffu, sD, o);
                sE += __shfl_xor_sync(0xffffffffu, sE, o);
            }
            if (lane == 0) {
                d_as[r0 + row] = sA;
                d_ad[r0 + row] = sD;
                d_attr[r0 + row] = sqrtf(sE);
            }
            d_hp[(r0 + row) * 64 + lane]      = hp0;
            d_hp[(r0 + row) * 64 + lane + 32] = hp1;
        }
    }
}

// ---------------- K2: streaming adj scan (best measured) ----------
__global__ __launch_bounds__(256) void k2_adj(const float* __restrict__ adj)
{
    const int r = blockIdx.x;
    const int tid = threadIdx.x;
    __shared__ int s_cnt;
    __shared__ int s_list[CAP];
    if (tid == 0) s_cnt = 0;
    __syncthreads();
    const float4* row = (const float4*)(adj + (size_t)r * N);

    float4 v[8];
    #pragma unroll
    for (int it = 0; it < 8; it++)
        v[it] = __ldcs(&row[tid + it * 256]);

    #pragma unroll
    for (int it = 0; it < 8; it++) {
        int jb = (tid + it * 256) << 2;
        if (v[it].x > 0.f) { int p = atomicAdd(&s_cnt, 1); if (p < CAP) s_list[p] = jb; }
        if (v[it].y > 0.f) { int p = atomicAdd(&s_cnt, 1); if (p < CAP) s_list[p] = jb + 1; }
        if (v[it].z > 0.f) { int p = atomicAdd(&s_cnt, 1); if (p < CAP) s_list[p] = jb + 2; }
        if (v[it].w > 0.f) { int p = atomicAdd(&s_cnt, 1); if (p < CAP) s_list[p] = jb + 3; }
    }
    __syncthreads();
    int cnt = min(s_cnt, CAP);
    if (tid == 0) d_row_cnt[r] = cnt;
    for (int t = tid; t < cnt; t += 256) {
        int j = s_list[t];
        d_row_list[r * CAP + t] = j;
        int slot = atomicAdd(&d_col_cnt[j], 1);
        if (slot < CAP) d_col_list[j * CAP + slot] = r;
    }
}

// ---------------- K3: sparse masked softmax over sources + emb ----------------
__global__ __launch_bounds__(256) void k3_attn(const float* __restrict__ bgat)
{
    __shared__ float sh_e[8][CAP];
    __shared__ int   sh_i[8][CAP];
    const int lane = threadIdx.x & 31;
    const int wl = threadIdx.x >> 5;
    const int j = blockIdx.x * 8 + wl;
    int cnt = min(d_col_cnt[j], CAP);
    float adv = d_ad[j];
    float m = -1e30f;
    for (int t = lane; t < cnt; t += 32) {
        int i = d_col_list[j * CAP + t];
        float e = d_as[i] + adv;
        e = e > 0.f ? e : 0.2f * e;     // leaky_relu(0.2)
        sh_e[wl][t] = e; sh_i[wl][t] = i;
        m = fmaxf(m, e);
    }
    float eself = d_as[j] + adv; eself = eself > 0.f ? eself : 0.2f * eself;
    m = fmaxf(m, eself);
    #pragma unroll
    for (int o = 16; o; o >>= 1) m = fmaxf(m, __shfl_xor_sync(0xffffffffu, m, o));
    float wsum = (lane == 0) ? __expf(eself - m) : 0.f;
    for (int t = lane; t < cnt; t += 32) {
        float ex = __expf(sh_e[wl][t] - m);
        sh_e[wl][t] = ex;
        wsum += ex;
    }
    #pragma unroll
    for (int o = 16; o; o >>= 1) wsum += __shfl_xor_sync(0xffffffffu, wsum, o);
    __syncwarp();
    float inv = __fdividef(1.f, wsum);
    float exself = __expf(eself - m);
    float acc0 = exself * d_hp[j * 64 + lane];
    float acc1 = exself * d_hp[j * 64 + lane + 32];
    for (int t = 0; t < cnt; t++) {
        int i = sh_i[wl][t];
        float ex = sh_e[wl][t];
        acc0 += ex * d_hp[i * 64 + lane];
        acc1 += ex * d_hp[i * 64 + lane + 32];
    }
    float e0 = acc0 * inv + bgat[lane];
    float e1 = acc1 * inv + bgat[lane + 32];
    d_emb[j * 64 + lane]      = e0;
    d_emb[j * 64 + lane + 32] = e1;
    d_embh[j * 64 + lane]      = __float2bfloat16(e0);
    d_embh[j * 64 + lane + 32] = __float2bfloat16(e1);
}

// ---------------- K4: symmetric emb@emb^T, M=32 rows/warp -------------------
// ncu showed L1/smem-bound (67.8%): each warp previously re-read the whole B
// tile. Now 4 warps x 32 rows: each B ldsm feeds 2 MMAs -> B smem traffic
// halves. 128 threads/block, same 128x128 tile, same math per element.
#define TPAD 72

__device__ __forceinline__ void ldsm4(uint32_t& r0, uint32_t& r1, uint32_t& r2,
                                      uint32_t& r3, const void* p)
{
    uint32_t addr = (uint32_t)__cvta_generic_to_shared(p);
    asm volatile("ldmatrix.sync.aligned.m8n8.x4.shared.b16 {%0,%1,%2,%3}, [%4];"
                 : "=r"(r0), "=r"(r1), "=r"(r2), "=r"(r3) : "r"(addr));
}

__device__ __forceinline__ void mma16816(float* c, const uint32_t* a,
                                         uint32_t b0, uint32_t b1)
{
    asm volatile(
        "mma.sync.aligned.m16n8k16.row.col.f32.bf16.bf16.f32 "
        "{%0,%1,%2,%3}, {%4,%5,%6,%7}, {%8,%9}, {%0,%1,%2,%3};"
        : "+f"(c[0]), "+f"(c[1]), "+f"(c[2]), "+f"(c[3])
        : "r"(a[0]), "r"(a[1]), "r"(a[2]), "r"(a[3]), "r"(b0), "r"(b1));
}

// sigmoid(z)^2 via single-MUFU tanh.approx: sig = 0.5 + 0.5*tanh(z/2)
__device__ __forceinline__ float sig2_fast(float z) {
    float t;
    asm("tanh.approx.f32 %0, %1;" : "=f"(t) : "f"(0.5f * z));
    float s = fmaf(0.5f, t, 0.5f);
    return s * s;
}

__global__ __launch_bounds__(128) void k4_tri()
{
    const int bi = blockIdx.x, bj = blockIdx.y;
    if (bj < bi) return;                    // upper triangle only
    const bool diag = (bi == bj);

    __shared__ __align__(16) __nv_bfloat16 sA[128 * TPAD];
    __shared__ __align__(16) __nv_bfloat16 sB[128 * TPAD];
    __shared__ float scol[4][128];          // per-warp column sums (no atomics)
    const int tid = threadIdx.x;            // 0..127
    const int lane = tid & 31, w = tid >> 5;  // 4 warps
    const int r0 = bi * 128, c0 = bj * 128;

    // load A tile: 1024 uint4 over 128 threads = 8 iterations
    #pragma unroll
    for (int it = 0; it < 8; it++) {
        int idx = tid + it * 128;
        int row = idx >> 3, kc = (idx & 7) * 8;
        *(uint4*)&sA[row * TPAD + kc] = *(const uint4*)&d_embh[(r0 + row) * 64 + kc];
    }
    if (!diag) {
        #pragma unroll
        for (int it = 0; it < 8; it++) {
            int idx = tid + it * 128;
            int row = idx >> 3, kc = (idx & 7) * 8;
            *(uint4*)&sB[row * TPAD + kc] = *(const uint4*)&d_embh[(c0 + row) * 64 + kc];
        }
    }
    __syncthreads();

    const __nv_bfloat16* Bp = diag ? sA : sB;

    // A fragments: warp w covers rows 32w..32w+31 = two 16-row groups
    uint32_t aF[2][4][4];
    {
        int m = lane >> 3, rr = lane & 7;
        int koff = (m >> 1) * 8;
        #pragma unroll
        for (int rg = 0; rg < 2; rg++) {
            int arow = 32 * w + 16 * rg + rr + (m & 1) * 8;
            #pragma unroll
            for (int s = 0; s < 4; s++)
                ldsm4(aF[rg][s][0], aF[rg][s][1], aF[rg][s][2], aF[rg][s][3],
                      &sA[arow * TPAD + s * 16 + koff]);
        }
    }

    const int m = lane >> 3, rr = lane & 7;
    const int brow = rr + ((m >> 1) & 1) * 8;
    const int bkoff = (m & 1) * 8;

    float racc[2][2] = {{0.f, 0.f}, {0.f, 0.f}};   // [rowgroup][0: rows+0..7, 1: rows+8..15]

    #pragma unroll
    for (int fp = 0; fp < 8; fp++) {
        float acc2[2][2][4];
        #pragma unroll
        for (int rg = 0; rg < 2; rg++)
            #pragma unroll
            for (int i = 0; i < 2; i++)
                #pragma unroll
                for (int q = 0; q < 4; q++) acc2[rg][i][q] = 0.f;

        #pragma unroll
        for (int s = 0; s < 4; s++) {
            uint32_t b0, b1, b2, b3;
            ldsm4(b0, b1, b2, b3,
                  &Bp[(fp * 16 + brow) * TPAD + s * 16 + bkoff]);
            #pragma unroll
            for (int rg = 0; rg < 2; rg++) {
                mma16816(acc2[rg][0], aF[rg][s], b0, b1);
                mma16816(acc2[rg][1], aF[rg][s], b2, b3);
            }
        }

        // epilogue for this 16-column fragment pair (both row groups)
        #pragma unroll
        for (int i = 0; i < 2; i++) {          // i=0 -> cols fp*16+0..7, i=1 -> +8..15
            float cs0 = 0.f, cs1 = 0.f;
            #pragma unroll
            for (int rg = 0; rg < 2; rg++) {
                float v0 = sig2_fast(acc2[rg][i][0]), v1 = sig2_fast(acc2[rg][i][1]);
                float v2 = sig2_fast(acc2[rg][i][2]), v3 = sig2_fast(acc2[rg][i][3]);
                racc[rg][0] += v0 + v1;
                racc[rg][1] += v2 + v3;
                cs0 += v0 + v2;
                cs1 += v1 + v3;
            }
            if (!diag) {
                cs0 += __shfl_xor_sync(0xffffffffu, cs0, 4);
                cs0 += __shfl_xor_sync(0xffffffffu, cs0, 8);
                cs0 += __shfl_xor_sync(0xffffffffu, cs0, 16);
                cs1 += __shfl_xor_sync(0xffffffffu, cs1, 4);
                cs1 += __shfl_xor_sync(0xffffffffu, cs1, 8);
                cs1 += __shfl_xor_sync(0xffffffffu, cs1, 16);
                if (lane < 4) {
                    int colb = fp * 16 + i * 8 + lane * 2;
                    scol[w][colb]     = cs0;
                    scol[w][colb + 1] = cs1;
                }
            }
        }
    }

    // row sums: quad-reduce (lanes sharing output rows)
    #pragma unroll
    for (int rg = 0; rg < 2; rg++) {
        float r0s = racc[rg][0], r1s = racc[rg][1];
        r0s += __shfl_xor_sync(0xffffffffu, r0s, 1);
        r0s += __shfl_xor_sync(0xffffffffu, r0s, 2);
        r1s += __shfl_xor_sync(0xffffffffu, r1s, 1);
        r1s += __shfl_xor_sync(0xffffffffu, r1s, 2);
        if ((lane & 3) == 0) {
            int row = r0 + 32 * w + 16 * rg + (lane >> 2);
            atomicAdd(&d_t1[row], r0s);
            atomicAdd(&d_t1[row + 8], r1s);
        }
    }

    if (!diag) {
        __syncthreads();
        // 128 threads cover 128 columns
        float s = scol[0][tid] + scol[1][tid] + scol[2][tid] + scol[3][tid];
        atomicAdd(&d_t1[c0 + tid], s);
    }
}

// ---------------- K5: sparse t2 correction (overlapped with K4 on s1) ---------
__global__ __launch_bounds__(256) void k5_t2()
{
    const int lane = threadIdx.x & 31;
    const int r = blockIdx.x * 8 + (threadIdx.x >> 5);
    float e0 = d_emb[r * 64 + lane], e1 = d_emb[r * 64 + lane + 32];
    int cnt = d_row_cnt[r];
    float t2 = 0.f;
    for (int t = 0; t < cnt; t++) {
        int j = d_row_list[r * CAP + t];
        float p = e0 * d_emb[j * 64 + lane] + e1 * d_emb[j * 64 + lane + 32];
        #pragma unroll
        for (int o = 16; o; o >>= 1) p += __shfl_xor_sync(0xffffffffu, p, o);
        float u = __expf(-p);
        t2 += __fdividef(1.f, 1.f + u);
    }
    if (lane == 0) d_t2[r] = t2;
}

// ---------------- K6: fused score + loss + gather ----------------
__device__ __forceinline__ float node_score(int r) {
    float v = d_t1[r] - 2.f * d_t2[r] + (float)d_row_cnt[r];
    return 0.5f * d_attr[r] + 0.5f * sqrtf(fmaxf(v, 0.f));
}

__global__ void k6_out(const int* __restrict__ idxt, const int* __restrict__ idxs,
                       float* __restrict__ out)
{
    int tid = threadIdx.x;
    if (blockIdx.x == 0) {
        __shared__ float red[256];
        float s = 0.f;
        for (int i = tid; i < 4096; i += 256) s += node_score(idxt[i]);
        red[tid] = s; __syncthreads();
        for (int o = 128; o; o >>= 1) { if (tid < o) red[tid] += red[tid + o]; __syncthreads(); }
        if (tid == 0) out[0] = red[0] * (1.f / 4096.f);
    } else {
        int i = (blockIdx.x - 1) * 256 + tid;
        out[1 + i] = node_score(idxs[i]);
    }
}

// ---------------- K7: trailing reset — restores zero-state for next call -----
__global__ void k7_reset() {
    int i = blockIdx.x * blockDim.x + threadIdx.x;
    if (i < N) { d_col_cnt[i] = 0; d_t1[i] = 0.f; }
}

// ---------------- launch ----------------
extern "C" void kernel_launch(void* const* d_in, const int* in_sizes, int n_in,
                              void* d_out, int out_size)
{
    const float* seq1    = (const float*)d_in[0];
    const float* adj     = (const float*)d_in[1];
    const int* idx_train = (const int*)d_in[2];
    const int* idx_test  = (const int*)d_in[3];
    const float* W_stru  = (const float*)d_in[4];
    const float* b_stru  = (const float*)d_in[5];
    const float* W_gat   = (const float*)d_in[6];
    const float* att_src = (const float*)d_in[7];
    const float* att_dst = (const float*)d_in[8];
    const float* b_gat   = (const float*)d_in[9];
    const float* W_a1    = (const float*)d_in[10];
    const float* b_a1    = (const float*)d_in[11];
    const float* W_a2    = (const float*)d_in[12];
    const float* b_a2    = (const float*)d_in[13];
    float* out = (float*)d_out;

    const int k1_smem = K1_FLOATS * (int)sizeof(float);   // ~77.3 KB
    cudaFuncSetAttribute(k1_mlp, cudaFuncAttributeMaxDynamicSharedMemorySize, k1_smem);

    // fork 1: k1 (compute-bound, s1) concurrent with k2 (HBM-bound, stream 0).
    cudaEventRecord(g_res.e_fork, 0);
    cudaStreamWaitEvent(g_res.s1, g_res.e_fork, 0);
    k1_mlp<<<256, 256, k1_smem, g_res.s1>>>(seq1, W_stru, b_stru, W_gat,    // #1
                                            att_src, att_dst,
                                            W_a1, b_a1, W_a2, b_a2);
    cudaEventRecord(g_res.e_join, g_res.s1);

    k2_adj<<<8192, 256>>>(adj);                                             // #2

    // join 1, then attention
    cudaStreamWaitEvent(0, g_res.e_join, 0);
    k3_attn<<<1024, 256>>>(b_gat);                                          // #3

    // fork 2 around k4: k4 stays submission #4 so ncu keeps capturing it
    cudaEventRecord(g_res.e_k3, 0);
    k4_tri<<<dim3(64, 64), 128>>>();                                        // #4

    cudaStreamWaitEvent(g_res.s1, g_res.e_k3, 0);
    k5_t2<<<1024, 256, 0, g_res.s1>>>();                                    // #5
    cudaEventRecord(g_res.e_t2, g_res.s1);

    // join 2, then fused score/output, then trailing reset
    cudaStreamWaitEvent(0, g_res.e_t2, 0);
    k6_out<<<17, 256>>>(idx_train, idx_test, out);                          // #6
    k7_reset<<<32, 256>>>();                                                // #7
}

// round 16
// speedup vs baseline: 1.0295x; 1.0010x over previous
#include <cuda_runtime.h>
#include <cuda_bf16.h>
#include <cstdint>

#define N 8192
#define NIN 64
#define NH 128
#define CAP 128   // max degree capacity; deg ~ Poisson(16), P(>100) ~ 0

// ---------------- device scratch (no allocations allowed) ----------------
// d_col_cnt / d_t1 are zero at module load and re-zeroed by k7_reset at the
// END of every kernel_launch (after their last readers). Deterministic.
__device__ float d_hp[N * NIN];      // transformed features
__device__ float d_as[N];            // source attention terms
__device__ float d_ad[N];            // dst attention terms
__device__ float d_attr[N];          // attribute recon error per row
__device__ float d_emb[N * NIN];     // GAT output embeddings (fp32, for sparse path)
__device__ __nv_bfloat16 d_embh[N * NIN];  // bf16 copy for tensor-core GEMM
__device__ float d_t1[N];            // sum_j sigmoid(z)^2 per row
__device__ float d_t2[N];            // sum_{j in nbr} sigmoid(z) per row
__device__ int   d_col_cnt[N];
__device__ int   d_col_list[N * CAP];  // sources i per column j
__device__ int   d_row_cnt[N];
__device__ int   d_row_list[N * CAP];  // dsts j per row r

// ---- host-side stream/event resources (created once; no device memory) ----
struct GraphRes {
    cudaStream_t s1;
    cudaEvent_t e_fork, e_join, e_k3, e_t2;
    GraphRes() {
        cudaStreamCreateWithFlags(&s1, cudaStreamNonBlocking);
        cudaEventCreateWithFlags(&e_fork, cudaEventDisableTiming);
        cudaEventCreateWithFlags(&e_join, cudaEventDisableTiming);
        cudaEventCreateWithFlags(&e_k3, cudaEventDisableTiming);
        cudaEventCreateWithFlags(&e_t2, cudaEventDisableTiming);
    }
};
static GraphRes g_res;

// ---------------- K1: fused MLP branches, weights staged in smem ----------------
#define K1_SSEQ 0
#define K1_ACT1 (32 * 68)
#define K1_ACT2 (K1_ACT1 + 32 * 132)
#define K1_W    (K1_ACT2 + 32 * 132)
#define K1_FLOATS (K1_W + 128 * 68)

__global__ __launch_bounds__(256) void k1_mlp(
    const float* __restrict__ seq1,
    const float* __restrict__ Wst, const float* __restrict__ bst,
    const float* __restrict__ Wg,
    const float* __restrict__ asrc, const float* __restrict__ adst,
    const float* __restrict__ Wa1, const float* __restrict__ ba1,
    const float* __restrict__ Wa2, const float* __restrict__ ba2)
{
    extern __shared__ __align__(16) float sm[];
    float* sseq = sm + K1_SSEQ;
    float* sW   = sm + K1_W;
    const int tid = threadIdx.x;
    const int r0 = blockIdx.x * 32;

    for (int idx = tid; idx < 32 * 16; idx += 256) {
        int row = idx >> 4, k4 = (idx & 15) << 2;
        float4 v = *(const float4*)&seq1[(r0 + row) * 64 + k4];
        float* p = &sseq[row * 68 + k4];
        p[0] = v.x; p[1] = v.y; p[2] = v.z; p[3] = v.w;
    }

    // ---- phase 1 (x2 branches): 64 -> 128 ----
    #pragma unroll
    for (int br = 0; br < 2; br++) {
        const float* W = br ? Wa1 : Wst;
        const float* bb = br ? ba1 : bst;
        float* sAct = sm + (br ? K1_ACT2 : K1_ACT1);
        __syncthreads();
        for (int idx = tid; idx < 128 * 16; idx += 256) {
            int row = idx >> 4, k4 = (idx & 15) << 2;
            float4 v = *(const float4*)&W[row * 64 + k4];
            float* p = &sW[row * 68 + k4];
            p[0] = v.x; p[1] = v.y; p[2] = v.z; p[3] = v.w;
        }
        __syncthreads();

        int tx = tid & 31, ty = tid >> 5;
        float acc[4][4];
        #pragma unroll
        for (int j = 0; j < 4; j++) {
            float b = bb[tx * 4 + j];
            #pragma unroll
            for (int i = 0; i < 4; i++) acc[i][j] = b;
        }
        for (int k4 = 0; k4 < 64; k4 += 4) {
            float4 a[4];
            #pragma unroll
            for (int i = 0; i < 4; i++)
                a[i] = *(const float4*)&sseq[(ty * 4 + i) * 68 + k4];
            #pragma unroll
            for (int j = 0; j < 4; j++) {
                float4 w = *(const float4*)&sW[(tx * 4 + j) * 68 + k4];
                #pragma unroll
                for (int i = 0; i < 4; i++)
                    acc[i][j] += a[i].x * w.x + a[i].y * w.y + a[i].z * w.z + a[i].w * w.w;
            }
        }
        #pragma unroll
        for (int i = 0; i < 4; i++)
            #pragma unroll
            for (int j = 0; j < 4; j++)
                sAct[(ty * 4 + i) * 132 + tx * 4 + j] = fmaxf(acc[i][j], 0.f);
    }

    // ---- phase 2 (x2 branches): 128 -> 64 ----
    #pragma unroll
    for (int br = 0; br < 2; br++) {
        const float* W = br ? Wa2 : Wg;
        float* sAct = sm + (br ? K1_ACT2 : K1_ACT1);
        __syncthreads();
        for (int idx = tid; idx < 64 * 32; idx += 256) {
            int row = idx >> 5, k4 = (idx & 31) << 2;
            float4 v = *(const float4*)&W[row * 128 + k4];
            float* p = &sW[row * 132 + k4];
            p[0] = v.x; p[1] = v.y; p[2] = v.z; p[3] = v.w;
        }
        __syncthreads();

        int tx = tid & 15, ty = tid >> 4;
        float acc[2][4];
        #pragma unroll
        for (int j = 0; j < 4; j++) {
            float b = br ? ba2[tx * 4 + j] : 0.f;
            acc[0][j] = b; acc[1][j] = b;
        }
        for (int k4 = 0; k4 < 128; k4 += 4) {
            float4 a0 = *(const float4*)&sAct[(ty * 2 + 0) * 132 + k4];
            float4 a1 = *(const float4*)&sAct[(ty * 2 + 1) * 132 + k4];
            #pragma unroll
            for (int j = 0; j < 4; j++) {
                float4 w = *(const float4*)&sW[(tx * 4 + j) * 132 + k4];
                acc[0][j] += a0.x * w.x + a0.y * w.y + a0.z * w.z + a0.w * w.w;
                acc[1][j] += a1.x * w.x + a1.y * w.y + a1.z * w.z + a1.w * w.w;
            }
        }
        __syncthreads();
        #pragma unroll
        for (int i = 0; i < 2; i++)
            #pragma unroll
            for (int j = 0; j < 4; j++)
                sAct[(ty * 2 + i) * 132 + tx * 4 + j] = acc[i][j];
    }
    __syncthreads();

    // ---- per-row reductions ----
    {
        float* sh  = sm + K1_ACT1;
        float* sxa = sm + K1_ACT2;
        int warp = tid >> 5, lane = tid & 31;
        float as0 = asrc[lane], as1 = asrc[lane + 32];
        float ad0 = adst[lane], ad1 = adst[lane + 32];
        for (int rr = 0; rr < 4; rr++) {
            int row = warp * 4 + rr;
            float hp0 = sh[row * 132 + lane], hp1 = sh[row * 132 + lane + 32];
            float x0 = sxa[row * 132 + lane], x1 = sxa[row * 132 + lane + 32];
            float df0 = sseq[row * 68 + lane] - x0;
            float df1 = sseq[row * 68 + lane + 32] - x1;
            float sA = hp0 * as0 + hp1 * as1;
            float sD = hp0 * ad0 + hp1 * ad1;
            float sE = df0 * df0 + df1 * df1;
            #pragma unroll
            for (int o = 16; o; o >>= 1) {
                sA += __shfl_xor_sync(0xffffffffu, sA, o);
                sD += __shfl_xor_sync(0xffffffffu, sD, o);
                sE += __shfl_xor_sync(0xffffffffu, sE, o);
            }
            if (lane == 0) {
                d_as[r0 + row] = sA;
                d_ad[r0 + row] = sD;
                d_attr[r0 + row] = sqrtf(sE);
            }
            d_hp[(r0 + row) * 64 + lane]      = hp0;
            d_hp[(r0 + row) * 64 + lane + 32] = hp1;
        }
    }
}

// ---------------- K2: streaming adj scan (best measured) ----------
__global__ __launch_bounds__(256) void k2_adj(const float* __restrict__ adj)
{
    const int r = blockIdx.x;
    const int tid = threadIdx.x;
    __shared__ int s_cnt;
    __shared__ int s_list[CAP];
    if (tid == 0) s_cnt = 0;
    __syncthreads();
    const float4* row = (const float4*)(adj + (size_t)r * N);

    float4 v[8];
    #pragma unroll
    for (int it = 0; it < 8; it++)
        v[it] = __ldcs(&row[tid + it * 256]);

    #pragma unroll
    for (int it = 0; it < 8; it++) {
        int jb = (tid + it * 256) << 2;
        if (v[it].x > 0.f) { int p = atomicAdd(&s_cnt, 1); if (p < CAP) s_list[p] = jb; }
        if (v[it].y > 0.f) { int p = atomicAdd(&s_cnt, 1); if (p < CAP) s_list[p] = jb + 1; }
        if (v[it].z > 0.f) { int p = atomicAdd(&s_cnt, 1); if (p < CAP) s_list[p] = jb + 2; }
        if (v[it].w > 0.f) { int p = atomicAdd(&s_cnt, 1); if (p < CAP) s_list[p] = jb + 3; }
    }
    __syncthreads();
    int cnt = min(s_cnt, CAP);
    if (tid == 0) d_row_cnt[r] = cnt;
    for (int t = tid; t < cnt; t += 256) {
        int j = s_list[t];
        d_row_list[r * CAP + t] = j;
        int slot = atomicAdd(&d_col_cnt[j], 1);
        if (slot < CAP) d_col_list[j * CAP + slot] = r;
    }
}

// ---------------- K3: sparse masked softmax over sources + emb ----------------
__global__ __launch_bounds__(256) void k3_attn(const float* __restrict__ bgat)
{
    __shared__ float sh_e[8][CAP];
    __shared__ int   sh_i[8][CAP];
    const int lane = threadIdx.x & 31;
    const int wl = threadIdx.x >> 5;
    const int j = blockIdx.x * 8 + wl;
    int cnt = min(d_col_cnt[j], CAP);
    float adv = d_ad[j];
    float m = -1e30f;
    for (int t = lane; t < cnt; t += 32) {
        int i = d_col_list[j * CAP + t];
        float e = d_as[i] + adv;
        e = e > 0.f ? e : 0.2f * e;     // leaky_relu(0.2)
        sh_e[wl][t] = e; sh_i[wl][t] = i;
        m = fmaxf(m, e);
    }
    float eself = d_as[j] + adv; eself = eself > 0.f ? eself : 0.2f * eself;
    m = fmaxf(m, eself);
    #pragma unroll
    for (int o = 16; o; o >>= 1) m = fmaxf(m, __shfl_xor_sync(0xffffffffu, m, o));
    float wsum = (lane == 0) ? __expf(eself - m) : 0.f;
    for (int t = lane; t < cnt; t += 32) {
        float ex = __expf(sh_e[wl][t] - m);
        sh_e[wl][t] = ex;
        wsum += ex;
    }
    #pragma unroll
    for (int o = 16; o; o >>= 1) wsum += __shfl_xor_sync(0xffffffffu, wsum, o);
    __syncwarp();
    float inv = __fdividef(1.f, wsum);
    float exself = __expf(eself - m);
    float acc0 = exself * d_hp[j * 64 + lane];
    float acc1 = exself * d_hp[j * 64 + lane + 32];
    for (int t = 0; t < cnt; t++) {
        int i = sh_i[wl][t];
        float ex = sh_e[wl][t];
        acc0 += ex * d_hp[i * 64 + lane];
        acc1 += ex * d_hp[i * 64 + lane + 32];
    }
    float e0 = acc0 * inv + bgat[lane];
    float e1 = acc1 * inv + bgat[lane + 32];
    d_emb[j * 64 + lane]      = e0;
    d_emb[j * 64 + lane + 32] = e1;
    d_embh[j * 64 + lane]      = __float2bfloat16(e0);
    d_embh[j * 64 + lane + 32] = __float2bfloat16(e1);
}

// ---------------- K4: symmetric emb@emb^T, M=32 rows/warp, occ-capped --------
// R15 halved B smem traffic (L1 67.8% -> 44.6%) but regs=111 dropped occupancy
// to 22% -> latency-bound. __launch_bounds__(128, 5) caps regs ~102 so RF and
// smem both allow 5 blocks/SM (31% occ). Same math.
#define TPAD 72

__device__ __forceinline__ void ldsm4(uint32_t& r0, uint32_t& r1, uint32_t& r2,
                                      uint32_t& r3, const void* p)
{
    uint32_t addr = (uint32_t)__cvta_generic_to_shared(p);
    asm volatile("ldmatrix.sync.aligned.m8n8.x4.shared.b16 {%0,%1,%2,%3}, [%4];"
                 : "=r"(r0), "=r"(r1), "=r"(r2), "=r"(r3) : "r"(addr));
}

__device__ __forceinline__ void mma16816(float* c, const uint32_t* a,
                                         uint32_t b0, uint32_t b1)
{
    asm volatile(
        "mma.sync.aligned.m16n8k16.row.col.f32.bf16.bf16.f32 "
        "{%0,%1,%2,%3}, {%4,%5,%6,%7}, {%8,%9}, {%0,%1,%2,%3};"
        : "+f"(c[0]), "+f"(c[1]), "+f"(c[2]), "+f"(c[3])
        : "r"(a[0]), "r"(a[1]), "r"(a[2]), "r"(a[3]), "r"(b0), "r"(b1));
}

// sigmoid(z)^2 via single-MUFU tanh.approx: sig = 0.5 + 0.5*tanh(z/2)
__device__ __forceinline__ float sig2_fast(float z) {
    float t;
    asm("tanh.approx.f32 %0, %1;" : "=f"(t) : "f"(0.5f * z));
    float s = fmaf(0.5f, t, 0.5f);
    return s * s;
}

__global__ __launch_bounds__(128, 5) void k4_tri()
{
    const int bi = blockIdx.x, bj = blockIdx.y;
    if (bj < bi) return;                    // upper triangle only
    const bool diag = (bi == bj);

    __shared__ __align__(16) __nv_bfloat16 sA[128 * TPAD];
    __shared__ __align__(16) __nv_bfloat16 sB[128 * TPAD];
    __shared__ float scol[4][128];          // per-warp column sums (no atomics)
    const int tid = threadIdx.x;            // 0..127
    const int lane = tid & 31, w = tid >> 5;  // 4 warps
    const int r0 = bi * 128, c0 = bj * 128;

    // load A tile: 1024 uint4 over 128 threads = 8 iterations
    #pragma unroll
    for (int it = 0; it < 8; it++) {
        int idx = tid + it * 128;
        int row = idx >> 3, kc = (idx & 7) * 8;
        *(uint4*)&sA[row * TPAD + kc] = *(const uint4*)&d_embh[(r0 + row) * 64 + kc];
    }
    if (!diag) {
        #pragma unroll
        for (int it = 0; it < 8; it++) {
            int idx = tid + it * 128;
            int row = idx >> 3, kc = (idx & 7) * 8;
            *(uint4*)&sB[row * TPAD + kc] = *(const uint4*)&d_embh[(c0 + row) * 64 + kc];
        }
    }
    __syncthreads();

    const __nv_bfloat16* Bp = diag ? sA : sB;

    // A fragments: warp w covers rows 32w..32w+31 = two 16-row groups
    uint32_t aF[2][4][4];
    {
        int m = lane >> 3, rr = lane & 7;
        int koff = (m >> 1) * 8;
        #pragma unroll
        for (int rg = 0; rg < 2; rg++) {
            int arow = 32 * w + 16 * rg + rr + (m & 1) * 8;
            #pragma unroll
            for (int s = 0; s < 4; s++)
                ldsm4(aF[rg][s][0], aF[rg][s][1], aF[rg][s][2], aF[rg][s][3],
                      &sA[arow * TPAD + s * 16 + koff]);
        }
    }

    const int m = lane >> 3, rr = lane & 7;
    const int brow = rr + ((m >> 1) & 1) * 8;
    const int bkoff = (m & 1) * 8;

    float racc[2][2] = {{0.f, 0.f}, {0.f, 0.f}};   // [rowgroup][0: rows+0..7, 1: rows+8..15]

    #pragma unroll
    for (int fp = 0; fp < 8; fp++) {
        float acc2[2][2][4];
        #pragma unroll
        for (int rg = 0; rg < 2; rg++)
            #pragma unroll
            for (int i = 0; i < 2; i++)
                #pragma unroll
                for (int q = 0; q < 4; q++) acc2[rg][i][q] = 0.f;

        #pragma unroll
        for (int s = 0; s < 4; s++) {
            uint32_t b0, b1, b2, b3;
            ldsm4(b0, b1, b2, b3,
                  &Bp[(fp * 16 + brow) * TPAD + s * 16 + bkoff]);
            #pragma unroll
            for (int rg = 0; rg < 2; rg++) {
                mma16816(acc2[rg][0], aF[rg][s], b0, b1);
                mma16816(acc2[rg][1], aF[rg][s], b2, b3);
            }
        }

        // epilogue for this 16-column fragment pair (both row groups)
        #pragma unroll
        for (int i = 0; i < 2; i++) {          // i=0 -> cols fp*16+0..7, i=1 -> +8..15
            float cs0 = 0.f, cs1 = 0.f;
            #pragma unroll
            for (int rg = 0; rg < 2; rg++) {
                float v0 = sig2_fast(acc2[rg][i][0]), v1 = sig2_fast(acc2[rg][i][1]);
                float v2 = sig2_fast(acc2[rg][i][2]), v3 = sig2_fast(acc2[rg][i][3]);
                racc[rg][0] += v0 + v1;
                racc[rg][1] += v2 + v3;
                cs0 += v0 + v2;
                cs1 += v1 + v3;
            }
            if (!diag) {
                cs0 += __shfl_xor_sync(0xffffffffu, cs0, 4);
                cs0 += __shfl_xor_sync(0xffffffffu, cs0, 8);
                cs0 += __shfl_xor_sync(0xffffffffu, cs0, 16);
                cs1 += __shfl_xor_sync(0xffffffffu, cs1, 4);
                cs1 += __shfl_xor_sync(0xffffffffu, cs1, 8);
                cs1 += __shfl_xor_sync(0xffffffffu, cs1, 16);
                if (lane < 4) {
                    int colb = fp * 16 + i * 8 + lane * 2;
                    scol[w][colb]     = cs0;
                    scol[w][colb + 1] = cs1;
                }
            }
        }
    }

    // row sums: quad-reduce (lanes sharing output rows)
    #pragma unroll
    for (int rg = 0; rg < 2; rg++) {
        float r0s = racc[rg][0], r1s = racc[rg][1];
        r0s += __shfl_xor_sync(0xffffffffu, r0s, 1);
        r0s += __shfl_xor_sync(0xffffffffu, r0s, 2);
        r1s += __shfl_xor_sync(0xffffffffu, r1s, 1);
        r1s += __shfl_xor_sync(0xffffffffu, r1s, 2);
        if ((lane & 3) == 0) {
            int row = r0 + 32 * w + 16 * rg + (lane >> 2);
            atomicAdd(&d_t1[row], r0s);
            atomicAdd(&d_t1[row + 8], r1s);
        }
    }

    if (!diag) {
        __syncthreads();
        // 128 threads cover 128 columns
        float s = scol[0][tid] + scol[1][tid] + scol[2][tid] + scol[3][tid];
        atomicAdd(&d_t1[c0 + tid], s);
    }
}

// ---------------- K5: sparse t2 correction (overlapped with K4 on s1) ---------
__global__ __launch_bounds__(256) void k5_t2()
{
    const int lane = threadIdx.x & 31;
    const int r = blockIdx.x * 8 + (threadIdx.x >> 5);
    float e0 = d_emb[r * 64 + lane], e1 = d_emb[r * 64 + lane + 32];
    int cnt = d_row_cnt[r];
    float t2 = 0.f;
    for (int t = 0; t < cnt; t++) {
        int j = d_row_list[r * CAP + t];
        float p = e0 * d_emb[j * 64 + lane] + e1 * d_emb[j * 64 + lane + 32];
        #pragma unroll
        for (int o = 16; o; o >>= 1) p += __shfl_xor_sync(0xffffffffu, p, o);
        float u = __expf(-p);
        t2 += __fdividef(1.f, 1.f + u);
    }
    if (lane == 0) d_t2[r] = t2;
}

// ---------------- K6: fused score + loss + gather ----------------
__device__ __forceinline__ float node_score(int r) {
    float v = d_t1[r] - 2.f * d_t2[r] + (float)d_row_cnt[r];
    return 0.5f * d_attr[r] + 0.5f * sqrtf(fmaxf(v, 0.f));
}

__global__ void k6_out(const int* __restrict__ idxt, const int* __restrict__ idxs,
                       float* __restrict__ out)
{
    int tid = threadIdx.x;
    if (blockIdx.x == 0) {
        __shared__ float red[256];
        float s = 0.f;
        for (int i = tid; i < 4096; i += 256) s += node_score(idxt[i]);
        red[tid] = s; __syncthreads();
        for (int o = 128; o; o >>= 1) { if (tid < o) red[tid] += red[tid + o]; __syncthreads(); }
        if (tid == 0) out[0] = red[0] * (1.f / 4096.f);
    } else {
        int i = (blockIdx.x - 1) * 256 + tid;
        out[1 + i] = node_score(idxs[i]);
    }
}

// ---------------- K7: trailing reset — restores zero-state for next call -----
__global__ void k7_reset() {
    int i = blockIdx.x * blockDim.x + threadIdx.x;
    if (i < N) { d_col_cnt[i] = 0; d_t1[i] = 0.f; }
}

// ---------------- launch ----------------
extern "C" void kernel_launch(void* const* d_in, const int* in_sizes, int n_in,
                              void* d_out, int out_size)
{
    const float* seq1    = (const float*)d_in[0];
    const float* adj     = (const float*)d_in[1];
    const int* idx_train = (const int*)d_in[2];
    const int* idx_test  = (const int*)d_in[3];
    const float* W_stru  = (const float*)d_in[4];
    const float* b_stru  = (const float*)d_in[5];
    const float* W_gat   = (const float*)d_in[6];
    const float* att_src = (const float*)d_in[7];
    const float* att_dst = (const float*)d_in[8];
    const float* b_gat   = (const float*)d_in[9];
    const float* W_a1    = (const float*)d_in[10];
    const float* b_a1    = (const float*)d_in[11];
    const float* W_a2    = (const float*)d_in[12];
    const float* b_a2    = (const float*)d_in[13];
    float* out = (float*)d_out;

    const int k1_smem = K1_FLOATS * (int)sizeof(float);   // ~77.3 KB
    cudaFuncSetAttribute(k1_mlp, cudaFuncAttributeMaxDynamicSharedMemorySize, k1_smem);

    // fork 1: k1 (compute-bound, s1) concurrent with k2 (HBM-bound, stream 0).
    cudaEventRecord(g_res.e_fork, 0);
    cudaStreamWaitEvent(g_res.s1, g_res.e_fork, 0);
    k1_mlp<<<256, 256, k1_smem, g_res.s1>>>(seq1, W_stru, b_stru, W_gat,    // #1
                                            att_src, att_dst,
                                            W_a1, b_a1, W_a2, b_a2);
    cudaEventRecord(g_res.e_join, g_res.s1);

    k2_adj<<<8192, 256>>>(adj);                                             // #2

    // join 1, then attention
    cudaStreamWaitEvent(0, g_res.e_join, 0);
    k3_attn<<<1024, 256>>>(b_gat);                                          // #3

    // fork 2 around k4: k4 stays submission #4 so ncu keeps capturing it
    cudaEventRecord(g_res.e_k3, 0);
    k4_tri<<<dim3(64, 64), 128>>>();                                        // #4

    cudaStreamWaitEvent(g_res.s1, g_res.e_k3, 0);
    k5_t2<<<1024, 256, 0, g_res.s1>>>();                                    // #5
    cudaEventRecord(g_res.e_t2, g_res.s1);

    // join 2, then fused score/output, then trailing reset
    cudaStreamWaitEvent(0, g_res.e_t2, 0);
    k6_out<<<17, 256>>>(idx_train, idx_test, out);                          // #6
    k7_reset<<<32, 256>>>();                                                // #7
}

// round 17
// speedup vs baseline: 1.0313x; 1.0017x over previous
#include <cuda_runtime.h>
#include <cuda_bf16.h>
#include <cstdint>

#define N 8192
#define NIN 64
#define NH 128
#define CAP 128   // max degree capacity; deg ~ Poisson(16), P(>100) ~ 0

// ---------------- device scratch (no allocations allowed) ----------------
// d_col_cnt / d_t1 are zero at module load and re-zeroed by k7_reset at the
// END of every kernel_launch (after their last readers). Deterministic.
__device__ float d_hp[N * NIN];      // transformed features
__device__ float d_as[N];            // source attention terms
__device__ float d_ad[N];            // dst attention terms
__device__ float d_attr[N];          // attribute recon error per row
__device__ float d_emb[N * NIN];     // GAT output embeddings (fp32, for sparse path)
__device__ __nv_bfloat16 d_embh[N * NIN];  // bf16 copy for tensor-core GEMM
__device__ float d_t1[N];            // sum_j sigmoid(z)^2 per row
__device__ float d_t2[N];            // sum_{j in nbr} sigmoid(z) per row
__device__ int   d_col_cnt[N];
__device__ int   d_col_list[N * CAP];  // sources i per column j
__device__ int   d_row_cnt[N];
__device__ int   d_row_list[N * CAP];  // dsts j per row r

// ---- host-side stream/event resources (created once; no device memory) ----
struct GraphRes {
    cudaStream_t s1;
    cudaEvent_t e_fork, e_join, e_k3, e_t2;
    GraphRes() {
        cudaStreamCreateWithFlags(&s1, cudaStreamNonBlocking);
        cudaEventCreateWithFlags(&e_fork, cudaEventDisableTiming);
        cudaEventCreateWithFlags(&e_join, cudaEventDisableTiming);
        cudaEventCreateWithFlags(&e_k3, cudaEventDisableTiming);
        cudaEventCreateWithFlags(&e_t2, cudaEventDisableTiming);
    }
};
static GraphRes g_res;

// ---------------- K1: fused MLP branches, weights staged in smem ----------------
#define K1_SSEQ 0
#define K1_ACT1 (32 * 68)
#define K1_ACT2 (K1_ACT1 + 32 * 132)
#define K1_W    (K1_ACT2 + 32 * 132)
#define K1_FLOATS (K1_W + 128 * 68)

__global__ __launch_bounds__(256) void k1_mlp(
    const float* __restrict__ seq1,
    const float* __restrict__ Wst, const float* __restrict__ bst,
    const float* __restrict__ Wg,
    const float* __restrict__ asrc, const float* __restrict__ adst,
    const float* __restrict__ Wa1, const float* __restrict__ ba1,
    const float* __restrict__ Wa2, const float* __restrict__ ba2)
{
    extern __shared__ __align__(16) float sm[];
    float* sseq = sm + K1_SSEQ;
    float* sW   = sm + K1_W;
    const int tid = threadIdx.x;
    const int r0 = blockIdx.x * 32;

    for (int idx = tid; idx < 32 * 16; idx += 256) {
        int row = idx >> 4, k4 = (idx & 15) << 2;
        float4 v = *(const float4*)&seq1[(r0 + row) * 64 + k4];
        float* p = &sseq[row * 68 + k4];
        p[0] = v.x; p[1] = v.y; p[2] = v.z; p[3] = v.w;
    }

    // ---- phase 1 (x2 branches): 64 -> 128 ----
    #pragma unroll
    for (int br = 0; br < 2; br++) {
        const float* W = br ? Wa1 : Wst;
        const float* bb = br ? ba1 : bst;
        float* sAct = sm + (br ? K1_ACT2 : K1_ACT1);
        __syncthreads();
        for (int idx = tid; idx < 128 * 16; idx += 256) {
            int row = idx >> 4, k4 = (idx & 15) << 2;
            float4 v = *(const float4*)&W[row * 64 + k4];
            float* p = &sW[row * 68 + k4];
            p[0] = v.x; p[1] = v.y; p[2] = v.z; p[3] = v.w;
        }
        __syncthreads();

        int tx = tid & 31, ty = tid >> 5;
        float acc[4][4];
        #pragma unroll
        for (int j = 0; j < 4; j++) {
            float b = bb[tx * 4 + j];
            #pragma unroll
            for (int i = 0; i < 4; i++) acc[i][j] = b;
        }
        for (int k4 = 0; k4 < 64; k4 += 4) {
            float4 a[4];
            #pragma unroll
            for (int i = 0; i < 4; i++)
                a[i] = *(const float4*)&sseq[(ty * 4 + i) * 68 + k4];
            #pragma unroll
            for (int j = 0; j < 4; j++) {
                float4 w = *(const float4*)&sW[(tx * 4 + j) * 68 + k4];
                #pragma unroll
                for (int i = 0; i < 4; i++)
                    acc[i][j] += a[i].x * w.x + a[i].y * w.y + a[i].z * w.z + a[i].w * w.w;
            }
        }
        #pragma unroll
        for (int i = 0; i < 4; i++)
            #pragma unroll
            for (int j = 0; j < 4; j++)
                sAct[(ty * 4 + i) * 132 + tx * 4 + j] = fmaxf(acc[i][j], 0.f);
    }

    // ---- phase 2 (x2 branches): 128 -> 64 ----
    #pragma unroll
    for (int br = 0; br < 2; br++) {
        const float* W = br ? Wa2 : Wg;
        float* sAct = sm + (br ? K1_ACT2 : K1_ACT1);
        __syncthreads();
        for (int idx = tid; idx < 64 * 32; idx += 256) {
            int row = idx >> 5, k4 = (idx & 31) << 2;
            float4 v = *(const float4*)&W[row * 128 + k4];
            float* p = &sW[row * 132 + k4];
            p[0] = v.x; p[1] = v.y; p[2] = v.z; p[3] = v.w;
        }
        __syncthreads();

        int tx = tid & 15, ty = tid >> 4;
        float acc[2][4];
        #pragma unroll
        for (int j = 0; j < 4; j++) {
            float b = br ? ba2[tx * 4 + j] : 0.f;
            acc[0][j] = b; acc[1][j] = b;
        }
        for (int k4 = 0; k4 < 128; k4 += 4) {
            float4 a0 = *(const float4*)&sAct[(ty * 2 + 0) * 132 + k4];
            float4 a1 = *(const float4*)&sAct[(ty * 2 + 1) * 132 + k4];
            #pragma unroll
            for (int j = 0; j < 4; j++) {
                float4 w = *(const float4*)&sW[(tx * 4 + j) * 132 + k4];
                acc[0][j] += a0.x * w.x + a0.y * w.y + a0.z * w.z + a0.w * w.w;
                acc[1][j] += a1.x * w.x + a1.y * w.y + a1.z * w.z + a1.w * w.w;
            }
        }
        __syncthreads();
        #pragma unroll
        for (int i = 0; i < 2; i++)
            #pragma unroll
            for (int j = 0; j < 4; j++)
                sAct[(ty * 2 + i) * 132 + tx * 4 + j] = acc[i][j];
    }
    __syncthreads();

    // ---- per-row reductions ----
    {
        float* sh  = sm + K1_ACT1;
        float* sxa = sm + K1_ACT2;
        int warp = tid >> 5, lane = tid & 31;
        float as0 = asrc[lane], as1 = asrc[lane + 32];
        float ad0 = adst[lane], ad1 = adst[lane + 32];
        for (int rr = 0; rr < 4; rr++) {
            int row = warp * 4 + rr;
            float hp0 = sh[row * 132 + lane], hp1 = sh[row * 132 + lane + 32];
            float x0 = sxa[row * 132 + lane], x1 = sxa[row * 132 + lane + 32];
            float df0 = sseq[row * 68 + lane] - x0;
            float df1 = sseq[row * 68 + lane + 32] - x1;
            float sA = hp0 * as0 + hp1 * as1;
            float sD = hp0 * ad0 + hp1 * ad1;
            float sE = df0 * df0 + df1 * df1;
            #pragma unroll
            for (int o = 16; o; o >>= 1) {
                sA += __shfl_xor_sync(0xffffffffu, sA, o);
                sD += __shfl_xor_sync(0xffffffffu, sD, o);
                sE += __shfl_xor_sync(0xffffffffu, sE, o);
            }
            if (lane == 0) {
                d_as[r0 + row] = sA;
                d_ad[r0 + row] = sD;
                d_attr[r0 + row] = sqrtf(sE);
            }
            d_hp[(r0 + row) * 64 + lane]      = hp0;
            d_hp[(r0 + row) * 64 + lane + 32] = hp1;
        }
    }
}

// ---------------- K2: streaming adj scan (best measured) ----------
__global__ __launch_bounds__(256) void k2_adj(const float* __restrict__ adj)
{
    const int r = blockIdx.x;
    const int tid = threadIdx.x;
    __shared__ int s_cnt;
    __shared__ int s_list[CAP];
    if (tid == 0) s_cnt = 0;
    __syncthreads();
    const float4* row = (const float4*)(adj + (size_t)r * N);

    float4 v[8];
    #pragma unroll
    for (int it = 0; it < 8; it++)
        v[it] = __ldcs(&row[tid + it * 256]);

    #pragma unroll
    for (int it = 0; it < 8; it++) {
        int jb = (tid + it * 256) << 2;
        if (v[it].x > 0.f) { int p = atomicAdd(&s_cnt, 1); if (p < CAP) s_list[p] = jb; }
        if (v[it].y > 0.f) { int p = atomicAdd(&s_cnt, 1); if (p < CAP) s_list[p] = jb + 1; }
        if (v[it].z > 0.f) { int p = atomicAdd(&s_cnt, 1); if (p < CAP) s_list[p] = jb + 2; }
        if (v[it].w > 0.f) { int p = atomicAdd(&s_cnt, 1); if (p < CAP) s_list[p] = jb + 3; }
    }
    __syncthreads();
    int cnt = min(s_cnt, CAP);
    if (tid == 0) d_row_cnt[r] = cnt;
    for (int t = tid; t < cnt; t += 256) {
        int j = s_list[t];
        d_row_list[r * CAP + t] = j;
        int slot = atomicAdd(&d_col_cnt[j], 1);
        if (slot < CAP) d_col_list[j * CAP + slot] = r;
    }
}

// ---------------- K3: sparse masked softmax over sources + emb ----------------
__global__ __launch_bounds__(256) void k3_attn(const float* __restrict__ bgat)
{
    __shared__ float sh_e[8][CAP];
    __shared__ int   sh_i[8][CAP];
    const int lane = threadIdx.x & 31;
    const int wl = threadIdx.x >> 5;
    const int j = blockIdx.x * 8 + wl;
    int cnt = min(d_col_cnt[j], CAP);
    float adv = d_ad[j];
    float m = -1e30f;
    for (int t = lane; t < cnt; t += 32) {
        int i = d_col_list[j * CAP + t];
        float e = d_as[i] + adv;
        e = e > 0.f ? e : 0.2f * e;     // leaky_relu(0.2)
        sh_e[wl][t] = e; sh_i[wl][t] = i;
        m = fmaxf(m, e);
    }
    float eself = d_as[j] + adv; eself = eself > 0.f ? eself : 0.2f * eself;
    m = fmaxf(m, eself);
    #pragma unroll
    for (int o = 16; o; o >>= 1) m = fmaxf(m, __shfl_xor_sync(0xffffffffu, m, o));
    float wsum = (lane == 0) ? __expf(eself - m) : 0.f;
    for (int t = lane; t < cnt; t += 32) {
        float ex = __expf(sh_e[wl][t] - m);
        sh_e[wl][t] = ex;
        wsum += ex;
    }
    #pragma unroll
    for (int o = 16; o; o >>= 1) wsum += __shfl_xor_sync(0xffffffffu, wsum, o);
    __syncwarp();
    float inv = __fdividef(1.f, wsum);
    float exself = __expf(eself - m);
    float acc0 = exself * d_hp[j * 64 + lane];
    float acc1 = exself * d_hp[j * 64 + lane + 32];
    for (int t = 0; t < cnt; t++) {
        int i = sh_i[wl][t];
        float ex = sh_e[wl][t];
        acc0 += ex * d_hp[i * 64 + lane];
        acc1 += ex * d_hp[i * 64 + lane + 32];
    }
    float e0 = acc0 * inv + bgat[lane];
    float e1 = acc1 * inv + bgat[lane + 32];
    d_emb[j * 64 + lane]      = e0;
    d_emb[j * 64 + lane + 32] = e1;
    d_embh[j * 64 + lane]      = __float2bfloat16(e0);
    d_embh[j * 64 + lane + 32] = __float2bfloat16(e1);
}

// ---------------- K4: symmetric emb@emb^T, swizzled TPAD=64, 6 blocks/SM -----
// TPAD 72 (pad) -> 64 (XOR swizzle): tiles 18->16 KB, smem 39->34 KB, so smem
// allows 6 blocks/SM; __launch_bounds__(128,6) caps regs at 85 to match.
// Swizzle XOR value depends only on (row&7), which is constant per thread for
// all fragment reads -> one LOP3 per ldsm address, nothing in the hot chain.
__device__ __forceinline__ uint32_t swz(uint32_t byte_off) {
    return byte_off ^ ((byte_off >> 3) & 0x70);   // XOR bits[6:4] by row&7
}

__device__ __forceinline__ void ldsm4(uint32_t& r0, uint32_t& r1, uint32_t& r2,
                                      uint32_t& r3, const void* p)
{
    uint32_t addr = (uint32_t)__cvta_generic_to_shared(p);
    asm volatile("ldmatrix.sync.aligned.m8n8.x4.shared.b16 {%0,%1,%2,%3}, [%4];"
                 : "=r"(r0), "=r"(r1), "=r"(r2), "=r"(r3) : "r"(addr));
}

__device__ __forceinline__ void mma16816(float* c, const uint32_t* a,
                                         uint32_t b0, uint32_t b1)
{
    asm volatile(
        "mma.sync.aligned.m16n8k16.row.col.f32.bf16.bf16.f32 "
        "{%0,%1,%2,%3}, {%4,%5,%6,%7}, {%8,%9}, {%0,%1,%2,%3};"
        : "+f"(c[0]), "+f"(c[1]), "+f"(c[2]), "+f"(c[3])
        : "r"(a[0]), "r"(a[1]), "r"(a[2]), "r"(a[3]), "r"(b0), "r"(b1));
}

// sigmoid(z)^2 via single-MUFU tanh.approx: sig = 0.5 + 0.5*tanh(z/2)
__device__ __forceinline__ float sig2_fast(float z) {
    float t;
    asm("tanh.approx.f32 %0, %1;" : "=f"(t) : "f"(0.5f * z));
    float s = fmaf(0.5f, t, 0.5f);
    return s * s;
}

__global__ __launch_bounds__(128, 6) void k4_tri()
{
    const int bi = blockIdx.x, bj = blockIdx.y;
    if (bj < bi) return;                    // upper triangle only
    const bool diag = (bi == bj);

    __shared__ __align__(16) char sAraw[128 * 128];   // 128 rows x 128 B (swizzled)
    __shared__ __align__(16) char sBraw[128 * 128];
    __shared__ float scol[4][128];          // per-warp column sums (no atomics)
    const int tid = threadIdx.x;            // 0..127
    const int lane = tid & 31, w = tid >> 5;  // 4 warps
    const int r0 = bi * 128, c0 = bj * 128;

    // load A tile: 1024 uint4 over 128 threads, swizzled store
    #pragma unroll
    for (int it = 0; it < 8; it++) {
        int idx = tid + it * 128;
        int row = idx >> 3, c16 = (idx & 7) * 16;     // 16-byte chunk
        uint32_t off = swz(row * 128 + c16);
        *(uint4*)&sAraw[off] = *(const uint4*)&d_embh[(r0 + row) * 64 + c16 / 2];
    }
    if (!diag) {
        #pragma unroll
        for (int it = 0; it < 8; it++) {
            int idx = tid + it * 128;
            int row = idx >> 3, c16 = (idx & 7) * 16;
            uint32_t off = swz(row * 128 + c16);
            *(uint4*)&sBraw[off] = *(const uint4*)&d_embh[(c0 + row) * 64 + c16 / 2];
        }
    }
    __syncthreads();

    const char* Bp = diag ? sAraw : sBraw;

    // A fragments: warp w covers rows 32w..32w+31 = two 16-row groups
    uint32_t aF[2][4][4];
    {
        int mm = lane >> 3, rr = lane & 7;
        int koffb = (mm >> 1) * 16;                    // 8 elems = 16 bytes
        #pragma unroll
        for (int rg = 0; rg < 2; rg++) {
            int arow = 32 * w + 16 * rg + rr + (mm & 1) * 8;
            #pragma unroll
            for (int s = 0; s < 4; s++)
                ldsm4(aF[rg][s][0], aF[rg][s][1], aF[rg][s][2], aF[rg][s][3],
                      &sAraw[swz(arow * 128 + s * 32 + koffb)]);
        }
    }

    const int mm = lane >> 3, rr = lane & 7;
    const int brow = rr + ((mm >> 1) & 1) * 8;
    const int bkoffb = (mm & 1) * 16;

    float racc[2][2] = {{0.f, 0.f}, {0.f, 0.f}};   // [rowgroup][0: rows+0..7, 1: rows+8..15]

    #pragma unroll
    for (int fp = 0; fp < 8; fp++) {
        float acc2[2][2][4];
        #pragma unroll
        for (int rg = 0; rg < 2; rg++)
            #pragma unroll
            for (int i = 0; i < 2; i++)
                #pragma unroll
                for (int q = 0; q < 4; q++) acc2[rg][i][q] = 0.f;

        #pragma unroll
        for (int s = 0; s < 4; s++) {
            uint32_t b0, b1, b2, b3;
            ldsm4(b0, b1, b2, b3,
                  &Bp[swz((fp * 16 + brow) * 128 + s * 32 + bkoffb)]);
            #pragma unroll
            for (int rg = 0; rg < 2; rg++) {
                mma16816(acc2[rg][0], aF[rg][s], b0, b1);
                mma16816(acc2[rg][1], aF[rg][s], b2, b3);
            }
        }

        // epilogue for this 16-column fragment pair (both row groups)
        #pragma unroll
        for (int i = 0; i < 2; i++) {          // i=0 -> cols fp*16+0..7, i=1 -> +8..15
            float cs0 = 0.f, cs1 = 0.f;
            #pragma unroll
            for (int rg = 0; rg < 2; rg++) {
                float v0 = sig2_fast(acc2[rg][i][0]), v1 = sig2_fast(acc2[rg][i][1]);
                float v2 = sig2_fast(acc2[rg][i][2]), v3 = sig2_fast(acc2[rg][i][3]);
                racc[rg][0] += v0 + v1;
                racc[rg][1] += v2 + v3;
                cs0 += v0 + v2;
                cs1 += v1 + v3;
            }
            if (!diag) {
                cs0 += __shfl_xor_sync(0xffffffffu, cs0, 4);
                cs0 += __shfl_xor_sync(0xffffffffu, cs0, 8);
                cs0 += __shfl_xor_sync(0xffffffffu, cs0, 16);
                cs1 += __shfl_xor_sync(0xffffffffu, cs1, 4);
                cs1 += __shfl_xor_sync(0xffffffffu, cs1, 8);
                cs1 += __shfl_xor_sync(0xffffffffu, cs1, 16);
                if (lane < 4) {
                    int colb = fp * 16 + i * 8 + lane * 2;
                    scol[w][colb]     = cs0;
                    scol[w][colb + 1] = cs1;
                }
            }
        }
    }

    // row sums: quad-reduce (lanes sharing output rows)
    #pragma unroll
    for (int rg = 0; rg < 2; rg++) {
        float r0s = racc[rg][0], r1s = racc[rg][1];
        r0s += __shfl_xor_sync(0xffffffffu, r0s, 1);
        r0s += __shfl_xor_sync(0xffffffffu, r0s, 2);
        r1s += __shfl_xor_sync(0xffffffffu, r1s, 1);
        r1s += __shfl_xor_sync(0xffffffffu, r1s, 2);
        if ((lane & 3) == 0) {
            int row = r0 + 32 * w + 16 * rg + (lane >> 2);
            atomicAdd(&d_t1[row], r0s);
            atomicAdd(&d_t1[row + 8], r1s);
        }
    }

    if (!diag) {
        __syncthreads();
        // 128 threads cover 128 columns
        float s = scol[0][tid] + scol[1][tid] + scol[2][tid] + scol[3][tid];
        atomicAdd(&d_t1[c0 + tid], s);
    }
}

// ---------------- K5: sparse t2 correction (overlapped with K4 on s1) ---------
__global__ __launch_bounds__(256) void k5_t2()
{
    const int lane = threadIdx.x & 31;
    const int r = blockIdx.x * 8 + (threadIdx.x >> 5);
    float e0 = d_emb[r * 64 + lane], e1 = d_emb[r * 64 + lane + 32];
    int cnt = d_row_cnt[r];
    float t2 = 0.f;
    for (int t = 0; t < cnt; t++) {
        int j = d_row_list[r * CAP + t];
        float p = e0 * d_emb[j * 64 + lane] + e1 * d_emb[j * 64 + lane + 32];
        #pragma unroll
        for (int o = 16; o; o >>= 1) p += __shfl_xor_sync(0xffffffffu, p, o);
        float u = __expf(-p);
        t2 += __fdividef(1.f, 1.f + u);
    }
    if (lane == 0) d_t2[r] = t2;
}

// ---------------- K6: fused score + loss + gather ----------------
__device__ __forceinline__ float node_score(int r) {
    float v = d_t1[r] - 2.f * d_t2[r] + (float)d_row_cnt[r];
    return 0.5f * d_attr[r] + 0.5f * sqrtf(fmaxf(v, 0.f));
}

__global__ void k6_out(const int* __restrict__ idxt, const int* __restrict__ idxs,
                       float* __restrict__ out)
{
    int tid = threadIdx.x;
    if (blockIdx.x == 0) {
        __shared__ float red[256];
        float s = 0.f;
        for (int i = tid; i < 4096; i += 256) s += node_score(idxt[i]);
        red[tid] = s; __syncthreads();
        for (int o = 128; o; o >>= 1) { if (tid < o) red[tid] += red[tid + o]; __syncthreads(); }
        if (tid == 0) out[0] = red[0] * (1.f / 4096.f);
    } else {
        int i = (blockIdx.x - 1) * 256 + tid;
        out[1 + i] = node_score(idxs[i]);
    }
}

// ---------------- K7: trailing reset — restores zero-state for next call -----
__global__ void k7_reset() {
    int i = blockIdx.x * blockDim.x + threadIdx.x;
    if (i < N) { d_col_cnt[i] = 0; d_t1[i] = 0.f; }
}

// ---------------- launch ----------------
extern "C" void kernel_launch(void* const* d_in, const int* in_sizes, int n_in,
                              void* d_out, int out_size)
{
    const float* seq1    = (const float*)d_in[0];
    const float* adj     = (const float*)d_in[1];
    const int* idx_train = (const int*)d_in[2];
    const int* idx_test  = (const int*)d_in[3];
    const float* W_stru  = (const float*)d_in[4];
    const float* b_stru  = (const float*)d_in[5];
    const float* W_gat   = (const float*)d_in[6];
    const float* att_src = (const float*)d_in[7];
    const float* att_dst = (const float*)d_in[8];
    const float* b_gat   = (const float*)d_in[9];
    const float* W_a1    = (const float*)d_in[10];
    const float* b_a1    = (const float*)d_in[11];
    const float* W_a2    = (const float*)d_in[12];
    const float* b_a2    = (const float*)d_in[13];
    float* out = (float*)d_out;

    const int k1_smem = K1_FLOATS * (int)sizeof(float);   // ~77.3 KB
    cudaFuncSetAttribute(k1_mlp, cudaFuncAttributeMaxDynamicSharedMemorySize, k1_smem);

    // fork 1: k1 (compute-bound, s1) concurrent with k2 (HBM-bound, stream 0).
    cudaEventRecord(g_res.e_fork, 0);
    cudaStreamWaitEvent(g_res.s1, g_res.e_fork, 0);
    k1_mlp<<<256, 256, k1_smem, g_res.s1>>>(seq1, W_stru, b_stru, W_gat,    // #1
                                            att_src, att_dst,
                                            W_a1, b_a1, W_a2, b_a2);
    cudaEventRecord(g_res.e_join, g_res.s1);

    k2_adj<<<8192, 256>>>(adj);                                             // #2

    // join 1, then attention
    cudaStreamWaitEvent(0, g_res.e_join, 0);
    k3_attn<<<1024, 256>>>(b_gat);                                          // #3

    // fork 2 around k4: k4 stays submission #4 so ncu keeps capturing it
    cudaEventRecord(g_res.e_k3, 0);
    k4_tri<<<dim3(64, 64), 128>>>();                                        // #4

    cudaStreamWaitEvent(g_res.s1, g_res.e_k3, 0);
    k5_t2<<<1024, 256, 0, g_res.s1>>>();                                    // #5
    cudaEventRecord(g_res.e_t2, g_res.s1);

    // join 2, then fused score/output, then trailing reset
    cudaStreamWaitEvent(0, g_res.e_t2, 0);
    k6_out<<<17, 256>>>(idx_train, idx_test, out);                          // #6
    k7_reset<<<32, 256>>>();                                                // #7
}